// round 1
// baseline (speedup 1.0000x reference)
#include <cuda_runtime.h>

#define NN 100000
#define FF 256
#define DD 128
#define MM 10
#define BB 32768
#define KK 32

// ---------------- scratch (device globals; no allocation) ----------------
__device__ __align__(16) float g_flow_emb[NN * DD];   // 51.2 MB
__device__ __align__(16) float g_flow_all[NN * DD];   // 51.2 MB
__device__ __align__(16) float g_agg[BB * DD];        // 16 MB
__device__ float g_score[NN];
__device__ __align__(16) float g_char[MM * DD];
__device__ __align__(16) float g_Lat[2 * MM * DD];    // sigmoid lat table, 20 x 128

struct Ptrs {
    const float* wemb;
    const float* wchar;
    const float* lin1w;
    const int*   catr;
    const int*   catn;
    const int*   pa;
};
__device__ Ptrs g_ptrs;

// ---------------- K0: probe input ordering + zero accumulators ----------------
// Seven inputs have element count 32768. In setup_inputs (dict) order they are
// [item_id, cat_r, cat_n, PA, W_emb, W_char, lin1_w]; in reference-signature
// order they are [W_emb, W_char, lin1_w, item_id, cat_r, cat_n, PA].
// item_id entries are ints in [0,100000) -> as uint32 all < 100000. Float
// weights ~U(-0.088,0.088) have bit patterns >= 0x00800000. Deterministic probe.
__global__ void fixup_kernel(const void* s0, const void* s1, const void* s2,
                             const void* s3, const void* s4, const void* s5,
                             const void* s6) {
    if (threadIdx.x == 0) {
        const unsigned* u = (const unsigned*)s0;
        bool intlike = true;
        for (int i = 0; i < 64; i++) {
            if (u[i] >= 100000u) { intlike = false; break; }
        }
        Ptrs p;
        if (intlike) {
            // dict order: s0=item_id s1=cat_r s2=cat_n s3=PA s4=Wemb s5=Wchar s6=lin1w
            p.catr = (const int*)s1;  p.catn = (const int*)s2;  p.pa = (const int*)s3;
            p.wemb = (const float*)s4; p.wchar = (const float*)s5; p.lin1w = (const float*)s6;
        } else {
            // signature order: s0=Wemb s1=Wchar s2=lin1w s3=item_id s4=cat_r s5=cat_n s6=PA
            p.wemb = (const float*)s0; p.wchar = (const float*)s1; p.lin1w = (const float*)s2;
            p.catr = (const int*)s4;  p.catn = (const int*)s5;  p.pa = (const int*)s6;
        }
        g_ptrs = p;
    }
    for (int i = threadIdx.x; i < MM * DD; i += blockDim.x) g_char[i] = 0.f;
}

// ---------------- K1: flow_emb = feature @ W_emb + bias ----------------
// Classic 128x128x8 tiled SGEMM, 256 threads, 8x8 per thread.
__global__ __launch_bounds__(256) void sgemm_kernel(const float* __restrict__ A,
                                                    const float* __restrict__ bias) {
    __shared__ __align__(16) float As[8][132];
    __shared__ __align__(16) float Bs[8][132];
    const float* W = g_ptrs.wemb;
    const int tid  = threadIdx.x;
    const int row0 = blockIdx.x * 128;
    const int aRow = tid >> 1, aCol = (tid & 1) * 4;
    const int bRow = tid >> 5, bCol = (tid & 31) * 4;
    const int tx = tid & 15, ty = tid >> 4;

    float acc[8][8];
#pragma unroll
    for (int i = 0; i < 8; i++)
#pragma unroll
        for (int j = 0; j < 8; j++) acc[i][j] = 0.f;

    for (int kt = 0; kt < FF; kt += 8) {
        const int gr = row0 + aRow;
        float4 av = make_float4(0.f, 0.f, 0.f, 0.f);
        if (gr < NN) av = *(const float4*)(A + (size_t)gr * FF + kt + aCol);
        As[aCol + 0][aRow] = av.x;
        As[aCol + 1][aRow] = av.y;
        As[aCol + 2][aRow] = av.z;
        As[aCol + 3][aRow] = av.w;
        float4 bv = *(const float4*)(W + (size_t)(kt + bRow) * DD + bCol);
        *(float4*)(&Bs[bRow][bCol]) = bv;
        __syncthreads();
#pragma unroll
        for (int kk = 0; kk < 8; kk++) {
            float ra[8], rb[8];
            *(float4*)(ra)     = *(const float4*)(&As[kk][ty * 8]);
            *(float4*)(ra + 4) = *(const float4*)(&As[kk][ty * 8 + 4]);
            *(float4*)(rb)     = *(const float4*)(&Bs[kk][tx * 8]);
            *(float4*)(rb + 4) = *(const float4*)(&Bs[kk][tx * 8 + 4]);
#pragma unroll
            for (int i = 0; i < 8; i++)
#pragma unroll
                for (int j = 0; j < 8; j++) acc[i][j] += ra[i] * rb[j];
        }
        __syncthreads();
    }

#pragma unroll
    for (int i = 0; i < 8; i++) {
        const int gr = row0 + ty * 8 + i;
        if (gr < NN) {
#pragma unroll
            for (int j = 0; j < 8; j += 4) {
                const int gc = tx * 8 + j;
                float4 v;
                v.x = acc[i][j]     + bias[gc];
                v.y = acc[i][j + 1] + bias[gc + 1];
                v.z = acc[i][j + 2] + bias[gc + 2];
                v.w = acc[i][j + 3] + bias[gc + 3];
                *(float4*)(&g_flow_emb[(size_t)gr * DD + gc]) = v;
            }
        }
    }
}

// ---------------- K2: char_emb[m][d] = sum_n adj[m][n] * flow_emb[n][d] ----------------
__global__ __launch_bounds__(128) void char_kernel(const float* __restrict__ adj) {
    __shared__ float adj_s[MM][512];
    const int n0  = blockIdx.x * 512;
    const int tid = threadIdx.x;
    int limit = NN - n0;
    if (limit > 512) limit = 512;
    for (int m = 0; m < MM; m++)
        for (int j = tid; j < limit; j += 128)
            adj_s[m][j] = adj[(size_t)m * NN + n0 + j];
    __syncthreads();
    float acc[MM];
#pragma unroll
    for (int m = 0; m < MM; m++) acc[m] = 0.f;
    for (int j = 0; j < limit; j++) {
        const float v = g_flow_emb[(size_t)(n0 + j) * DD + tid];
#pragma unroll
        for (int m = 0; m < MM; m++) acc[m] += adj_s[m][j] * v;
    }
    for (int m = 0; m < MM; m++) atomicAdd(&g_char[m * DD + tid], acc[m]);
}

// ---------------- K3: Lat[c][p][d] = sigmoid(ce[c]@Wc_top + ce[p]@Wc_bot) ----------------
// Only 2 x 10 distinct (cat, PA) combinations exist.
__global__ __launch_bounds__(128) void lat_kernel() {
    __shared__ float ce[MM * DD];
    const int d = threadIdx.x;
    for (int i = d; i < MM * DD; i += 128) ce[i] = g_char[i];
    __syncthreads();
    const float* Wc = g_ptrs.wchar;
    float at[2];
    float bb[MM];
    for (int m = 0; m < MM; m++) {
        float a = 0.f, b = 0.f;
        for (int i = 0; i < DD; i++) {
            const float c0 = ce[m * DD + i];
            a += c0 * Wc[i * DD + d];
            b += c0 * Wc[(DD + i) * DD + d];
        }
        if (m < 2) at[m] = a;
        bb[m] = b;
    }
#pragma unroll
    for (int c = 0; c < 2; c++)
        for (int p = 0; p < MM; p++)
            g_Lat[(c * MM + p) * DD + d] = 1.f / (1.f + expf(-(at[c] + bb[p])));
}

// ---------------- K4: flow_all + per-node attention score ----------------
// flow_all[n] = 0.5*(flow_emb[n] + adj0[n]*ce0 + adj1[n]*ce1)
// score[n] = dot(flow_all[n], att1_w) + att1_b   (linear -> hoisted out of [B,K])
__global__ __launch_bounds__(256) void flowall_kernel(const float* __restrict__ adj,
                                                      const float* __restrict__ att1w,
                                                      const float* __restrict__ att1b) {
    const int warp = threadIdx.x >> 5, lane = threadIdx.x & 31;
    const int n = blockIdx.x * 8 + warp;
    if (n >= NN) return;
    float4 f  = ((const float4*)g_flow_emb)[n * 32 + lane];
    const float a0 = __ldg(&adj[n]);
    const float a1 = __ldg(&adj[NN + n]);
    float4 c0 = ((const float4*)g_char)[lane];
    float4 c1 = ((const float4*)g_char)[32 + lane];
    float4 v;
    v.x = 0.5f * (f.x + a0 * c0.x + a1 * c1.x);
    v.y = 0.5f * (f.y + a0 * c0.y + a1 * c1.y);
    v.z = 0.5f * (f.z + a0 * c0.z + a1 * c1.z);
    v.w = 0.5f * (f.w + a0 * c0.w + a1 * c1.w);
    ((float4*)g_flow_all)[n * 32 + lane] = v;
    float4 w4 = ((const float4*)att1w)[lane];
    float p = v.x * w4.x + v.y * w4.y + v.z * w4.z + v.w * w4.w;
#pragma unroll
    for (int o = 16; o; o >>= 1) p += __shfl_xor_sync(0xffffffffu, p, o);
    if (lane == 0) g_score[n] = p + att1b[0];
}

// ---------------- K5: per-row gather + softmax + weighted sum -> g_agg ----------------
// One warp per batch row; lane = 4 consecutive feature dims (float4 gather, 512B/row).
// flow_all (51.2 MB) fits in L2 -> gather is L2-bound.
__global__ __launch_bounds__(256) void agg_kernel(const int* __restrict__ history) {
    const int warp = threadIdx.x >> 5, lane = threadIdx.x & 31;
    const int b = blockIdx.x * 8 + warp;
    const int h = history[b * KK + lane];
    const float s = g_score[h];
    float mx = s;
#pragma unroll
    for (int o = 16; o; o >>= 1) mx = fmaxf(mx, __shfl_xor_sync(0xffffffffu, mx, o));
    const float e = expf(s - mx);
    float sum = e;
#pragma unroll
    for (int o = 16; o; o >>= 1) sum += __shfl_xor_sync(0xffffffffu, sum, o);
    const float att = e / sum;
    float4 acc = make_float4(0.f, 0.f, 0.f, 0.f);
    const float4* fa = (const float4*)g_flow_all;
#pragma unroll
    for (int k = 0; k < KK; k++) {
        const int   idx = __shfl_sync(0xffffffffu, h, k);
        const float w   = __shfl_sync(0xffffffffu, att, k);
        float4 f = fa[idx * 32 + lane];
        acc.x += w * f.x; acc.y += w * f.y; acc.z += w * f.z; acc.w += w * f.w;
    }
    ((float4*)g_agg)[b * 32 + lane] = acc;
}

// ---------------- K6: out = relu(agg @ (W1_top+W1_bot) + b1); preds fused ----------------
// concat(agg,agg)@W1 == agg@(W1[:D]+W1[D:]). Tiled SGEMM 128x128x8 with fused
// epilogue: pred_r/n[row] = dot(Lat[cat,pa], out[row]) via warp-shuffle reduce.
__global__ __launch_bounds__(256) void outpred_kernel(const float* __restrict__ lin1b,
                                                      float* __restrict__ out) {
    __shared__ __align__(16) float As[8][132];
    __shared__ __align__(16) float Bs[8][132];
    __shared__ __align__(16) float Lat_s[2 * MM * DD];
    __shared__ __align__(16) float lb_s[DD];
    const float* lw   = g_ptrs.lin1w;
    const int*   catr = g_ptrs.catr;
    const int*   catn = g_ptrs.catn;
    const int*   pav  = g_ptrs.pa;
    const int tid  = threadIdx.x;
    const int row0 = blockIdx.x * 128;
    for (int i = tid; i < 2 * MM * DD; i += 256) Lat_s[i] = g_Lat[i];
    if (tid < DD) lb_s[tid] = lin1b[tid];
    const int aRow = tid >> 1, aCol = (tid & 1) * 4;
    const int bRow = tid >> 5, bCol = (tid & 31) * 4;
    const int tx = tid & 15, ty = tid >> 4;

    float acc[8][8];
#pragma unroll
    for (int i = 0; i < 8; i++)
#pragma unroll
        for (int j = 0; j < 8; j++) acc[i][j] = 0.f;

    for (int kt = 0; kt < DD; kt += 8) {
        float4 av = *(const float4*)(g_agg + (size_t)(row0 + aRow) * DD + kt + aCol);
        As[aCol + 0][aRow] = av.x;
        As[aCol + 1][aRow] = av.y;
        As[aCol + 2][aRow] = av.z;
        As[aCol + 3][aRow] = av.w;
        float4 b0 = *(const float4*)(lw + (size_t)(kt + bRow) * DD + bCol);
        float4 b1 = *(const float4*)(lw + (size_t)(DD + kt + bRow) * DD + bCol);
        float4 bv = make_float4(b0.x + b1.x, b0.y + b1.y, b0.z + b1.z, b0.w + b1.w);
        *(float4*)(&Bs[bRow][bCol]) = bv;
        __syncthreads();
#pragma unroll
        for (int kk = 0; kk < 8; kk++) {
            float ra[8], rb[8];
            *(float4*)(ra)     = *(const float4*)(&As[kk][ty * 8]);
            *(float4*)(ra + 4) = *(const float4*)(&As[kk][ty * 8 + 4]);
            *(float4*)(rb)     = *(const float4*)(&Bs[kk][tx * 8]);
            *(float4*)(rb + 4) = *(const float4*)(&Bs[kk][tx * 8 + 4]);
#pragma unroll
            for (int i = 0; i < 8; i++)
#pragma unroll
                for (int j = 0; j < 8; j++) acc[i][j] += ra[i] * rb[j];
        }
        __syncthreads();
    }

    float pr[8], pn[8];
#pragma unroll
    for (int i = 0; i < 8; i++) {
        const int row = row0 + ty * 8 + i;
        const int cr  = catr[row];
        const int cn_ = catn[row];
        const int p_  = pav[row];
        const float4* Lr = (const float4*)&Lat_s[(cr * MM + p_) * DD];
        const float4* Ln = (const float4*)&Lat_s[(cn_ * MM + p_) * DD];
        float sr = 0.f, sn = 0.f;
#pragma unroll
        for (int jj = 0; jj < 2; jj++) {
            float4 l1 = Lr[tx * 2 + jj];
            float4 l2 = Ln[tx * 2 + jj];
            float4 bb = *(const float4*)&lb_s[tx * 8 + jj * 4];
            const float o0 = fmaxf(acc[i][jj * 4 + 0] + bb.x, 0.f);
            const float o1 = fmaxf(acc[i][jj * 4 + 1] + bb.y, 0.f);
            const float o2 = fmaxf(acc[i][jj * 4 + 2] + bb.z, 0.f);
            const float o3 = fmaxf(acc[i][jj * 4 + 3] + bb.w, 0.f);
            sr += l1.x * o0 + l1.y * o1 + l1.z * o2 + l1.w * o3;
            sn += l2.x * o0 + l2.y * o1 + l2.z * o2 + l2.w * o3;
        }
        pr[i] = sr;
        pn[i] = sn;
    }
#pragma unroll
    for (int off = 1; off < 16; off <<= 1) {
#pragma unroll
        for (int i = 0; i < 8; i++) {
            pr[i] += __shfl_xor_sync(0xffffffffu, pr[i], off);
            pn[i] += __shfl_xor_sync(0xffffffffu, pn[i], off);
        }
    }
    if (tx == 0) {
#pragma unroll
        for (int i = 0; i < 8; i++) {
            const int row = row0 + ty * 8 + i;
            out[row]      = pr[i];
            out[BB + row] = pn[i];
        }
    }
}

// ---------------- host ----------------
extern "C" void kernel_launch(void* const* d_in, const int* in_sizes, int n_in,
                              void* d_out, int out_size) {
    const float* feat = nullptr;
    const float* adj  = nullptr;
    const int*   hist = nullptr;
    const float* b1   = nullptr;
    const void*  s32[8] = {nullptr};
    int n32 = 0;
    const float* s128[4] = {nullptr};
    int n128 = 0;

    for (int i = 0; i < n_in; i++) {
        const int sz = in_sizes[i];
        if (sz == NN * FF)      feat = (const float*)d_in[i];
        else if (sz == MM * NN) adj  = (const float*)d_in[i];
        else if (sz == BB * KK) hist = (const int*)d_in[i];
        else if (sz == BB)      { if (n32 < 8)  s32[n32++]  = d_in[i]; }
        else if (sz == DD)      { if (n128 < 4) s128[n128++] = (const float*)d_in[i]; }
        else if (sz == 1)       b1 = (const float*)d_in[i];
    }
    // size-128 inputs keep the same relative order in both candidate layouts:
    const float* bemb  = s128[0];
    const float* att1w = s128[1];
    const float* lin1b = s128[2];

    fixup_kernel<<<1, 256>>>(s32[0], s32[1], s32[2], s32[3], s32[4], s32[5], s32[6]);
    sgemm_kernel<<<(NN + 127) / 128, 256>>>(feat, bemb);
    char_kernel<<<(NN + 511) / 512, 128>>>(adj);
    lat_kernel<<<1, 128>>>();
    flowall_kernel<<<(NN + 7) / 8, 256>>>(adj, att1w, b1);
    agg_kernel<<<BB / 8, 256>>>(hist);
    outpred_kernel<<<BB / 128, 256>>>(lin1b, (float*)d_out);
}

// round 2
// speedup vs baseline: 1.2416x; 1.2416x over previous
#include <cuda_runtime.h>

#define NN 100000
#define FF 256
#define DD 128
#define MM 10
#define BB 32768
#define KK 32

// ---------------- scratch (device globals; no allocation) ----------------
__device__ __align__(16) float g_flow_all[NN * DD];   // 51.2 MB
__device__ __align__(16) float g_agg[BB * DD];        // 16 MB
__device__ float g_score[NN];
__device__ __align__(16) float g_char[MM * DD];
__device__ __align__(16) float g_Lat[2 * MM * DD];    // sigmoid lat table, 20 x 128
__device__ __align__(16) float g_cefeat[MM * FF];     // adj @ feature
__device__ float g_rowsum[MM];
__device__ __align__(16) float g_at[2 * DD];
__device__ __align__(16) float g_bb[MM * DD];

struct Ptrs {
    const float* wemb;
    const float* wchar;
    const float* lin1w;
    const int*   catr;
    const int*   catn;
    const int*   pa;
};
__device__ Ptrs g_ptrs;

__device__ __forceinline__ float tf32r(float x) {
    unsigned u;
    asm("cvt.rna.tf32.f32 %0, %1;" : "=r"(u) : "f"(x));
    return __uint_as_float(u);
}

// ---------------- K0: probe input ordering + zero accumulators ----------------
// Seven inputs have element count 32768; disambiguate dict-order vs signature-order
// by probing whether the first candidate looks like item_id ints (< 100000).
__global__ void fixup_kernel(const void* s0, const void* s1, const void* s2,
                             const void* s3, const void* s4, const void* s5,
                             const void* s6) {
    if (threadIdx.x == 0) {
        const unsigned* u = (const unsigned*)s0;
        bool intlike = true;
        for (int i = 0; i < 64; i++) {
            if (u[i] >= 100000u) { intlike = false; break; }
        }
        Ptrs p;
        if (intlike) {
            // dict order: s0=item_id s1=cat_r s2=cat_n s3=PA s4=Wemb s5=Wchar s6=lin1w
            p.catr = (const int*)s1;  p.catn = (const int*)s2;  p.pa = (const int*)s3;
            p.wemb = (const float*)s4; p.wchar = (const float*)s5; p.lin1w = (const float*)s6;
        } else {
            // signature order: s0=Wemb s1=Wchar s2=lin1w s3=item_id s4=cat_r s5=cat_n s6=PA
            p.wemb = (const float*)s0; p.wchar = (const float*)s1; p.lin1w = (const float*)s2;
            p.catr = (const int*)s4;  p.catn = (const int*)s5;  p.pa = (const int*)s6;
        }
        g_ptrs = p;
    }
    for (int i = threadIdx.x; i < MM * FF; i += blockDim.x) g_cefeat[i] = 0.f;
    if (threadIdx.x < MM) g_rowsum[threadIdx.x] = 0.f;
}

// ---------------- K1: ce_feat = adj @ feature  [10,256]; rowsum[10] ----------------
__global__ __launch_bounds__(256) void adjfeat_kernel(const float* __restrict__ adj,
                                                      const float* __restrict__ feat) {
    __shared__ float adj_s[MM][512];
    const int n0  = blockIdx.x * 512;
    const int tid = threadIdx.x;
    int limit = NN - n0;
    if (limit > 512) limit = 512;
    for (int m = 0; m < MM; m++)
        for (int j = tid; j < limit; j += 256)
            adj_s[m][j] = adj[(size_t)m * NN + n0 + j];
    __syncthreads();
    float acc[MM];
#pragma unroll
    for (int m = 0; m < MM; m++) acc[m] = 0.f;
    for (int j = 0; j < limit; j++) {
        const float v = feat[(size_t)(n0 + j) * FF + tid];
#pragma unroll
        for (int m = 0; m < MM; m++) acc[m] += adj_s[m][j] * v;
    }
#pragma unroll
    for (int m = 0; m < MM; m++) atomicAdd(&g_cefeat[m * FF + tid], acc[m]);
    // row sums of adj
    const int warp = tid >> 5, lane = tid & 31;
    for (int m = warp; m < MM; m += 8) {
        float s = 0.f;
        for (int j = lane; j < limit; j += 32) s += adj_s[m][j];
#pragma unroll
        for (int o = 16; o; o >>= 1) s += __shfl_xor_sync(0xffffffffu, s, o);
        if (lane == 0) atomicAdd(&g_rowsum[m], s);
    }
}

// ---------------- K2: char[m][d] = ce_feat[m] @ Wemb[:,d] + rowsum[m]*bias[d] ----------------
__global__ __launch_bounds__(128) void char_kernel2(const float* __restrict__ bias) {
    __shared__ float ce[FF];
    const int m = blockIdx.x, d = threadIdx.x;
    for (int i = d; i < FF; i += 128) ce[i] = g_cefeat[m * FF + i];
    __syncthreads();
    const float* W = g_ptrs.wemb;
    float s = 0.f;
#pragma unroll 4
    for (int k = 0; k < FF; k++) s += ce[k] * W[(size_t)k * DD + d];
    g_char[m * DD + d] = s + g_rowsum[m] * bias[d];
}

// ---------------- K3: at[c] = char[c]@Wc_top ; bb[m] = char[m]@Wc_bot ----------------
__global__ __launch_bounds__(128) void lat_kernel2() {
    __shared__ float ch[DD];
    const int b = blockIdx.x, d = threadIdx.x;
    const float* Wc = g_ptrs.wchar;
    if (b < 2) {
        for (int i = d; i < DD; i += 128) ch[i] = g_char[b * DD + i];
        __syncthreads();
        float s = 0.f;
#pragma unroll 4
        for (int i = 0; i < DD; i++) s += ch[i] * Wc[(size_t)i * DD + d];
        g_at[b * DD + d] = s;
    } else {
        const int m = b - 2;
        for (int i = d; i < DD; i += 128) ch[i] = g_char[m * DD + i];
        __syncthreads();
        float s = 0.f;
#pragma unroll 4
        for (int i = 0; i < DD; i++) s += ch[i] * Wc[(size_t)(DD + i) * DD + d];
        g_bb[m * DD + d] = s;
    }
}

// ---------------- K4: Lat table = sigmoid(at[c] + bb[p]) for 20 combos ----------------
__global__ void sig_kernel() {
    const int i = blockIdx.x * 256 + threadIdx.x;   // < 2560
    if (i >= 2 * MM * DD) return;
    const int d  = i & 127;
    const int p  = (i >> 7) % MM;
    const int cc = i / (MM * DD);
    g_Lat[i] = 1.f / (1.f + expf(-(g_at[cc * DD + d] + g_bb[p * DD + d])));
}

// ---------------- K5: TF32 tensor-core GEMM, fused flow_all + score epilogue ----
// flow_emb = feature @ Wemb + bias
// flow_all = 0.5*(flow_emb + adj0*char0 + adj1*char1)     (written)
// score[n] = flow_all[n] . att1_w + att1_b                 (written)
// Block: 256 thr (8 warps), tile M=128 x N=128, K chunks of 32 via smem.
// Warp w: rows [w*16, w*16+16), 16 n-tiles of mma.m16n8k8.tf32 -> 64 accum regs.
__global__ __launch_bounds__(256) void gemm_fused(const float* __restrict__ A,
                                                  const float* __restrict__ bias,
                                                  const float* __restrict__ adj,
                                                  const float* __restrict__ att1w,
                                                  const float* __restrict__ att1b) {
    __shared__ float As[128][36];    // padded: frag banks (4m+k)%32 conflict-free
    __shared__ float Bs[32][136];    // padded: frag banks (8k+n)%32 conflict-free
    __shared__ float att_s[DD], bias_s[DD], ch_s[2][DD];
    const float* W = g_ptrs.wemb;
    const int tid  = threadIdx.x;
    const int warp = tid >> 5, lane = tid & 31;
    const int gid  = lane >> 2, tig = lane & 3;
    const int row0 = blockIdx.x * 128;
    if (tid < DD) {
        att_s[tid]   = att1w[tid];
        bias_s[tid]  = bias[tid];
        ch_s[0][tid] = g_char[tid];
        ch_s[1][tid] = g_char[DD + tid];
    }

    float c[16][4];
#pragma unroll
    for (int nt = 0; nt < 16; nt++)
#pragma unroll
        for (int j = 0; j < 4; j++) c[nt][j] = 0.f;

    for (int kt = 0; kt < FF; kt += 32) {
        // load A tile 128x32 (4 passes x 32 rows), tf32-rounded
#pragma unroll
        for (int p = 0; p < 4; p++) {
            const int r  = p * 32 + (tid >> 3);
            const int cc = (tid & 7) * 4;
            const int gr = row0 + r;
            float4 v = make_float4(0.f, 0.f, 0.f, 0.f);
            if (gr < NN) v = *(const float4*)(A + (size_t)gr * FF + kt + cc);
            As[r][cc + 0] = tf32r(v.x);
            As[r][cc + 1] = tf32r(v.y);
            As[r][cc + 2] = tf32r(v.z);
            As[r][cc + 3] = tf32r(v.w);
        }
        // load B tile 32x128
#pragma unroll
        for (int p = 0; p < 4; p++) {
            const int r  = p * 8 + (tid >> 5);
            const int cc = (tid & 31) * 4;
            float4 v = *(const float4*)(W + (size_t)(kt + r) * DD + cc);
            Bs[r][cc + 0] = tf32r(v.x);
            Bs[r][cc + 1] = tf32r(v.y);
            Bs[r][cc + 2] = tf32r(v.z);
            Bs[r][cc + 3] = tf32r(v.w);
        }
        __syncthreads();
#pragma unroll
        for (int kk = 0; kk < 32; kk += 8) {
            const unsigned a0 = __float_as_uint(As[warp * 16 + gid    ][kk + tig    ]);
            const unsigned a1 = __float_as_uint(As[warp * 16 + gid + 8][kk + tig    ]);
            const unsigned a2 = __float_as_uint(As[warp * 16 + gid    ][kk + tig + 4]);
            const unsigned a3 = __float_as_uint(As[warp * 16 + gid + 8][kk + tig + 4]);
#pragma unroll
            for (int nt = 0; nt < 16; nt++) {
                const unsigned b0 = __float_as_uint(Bs[kk + tig    ][nt * 8 + gid]);
                const unsigned b1 = __float_as_uint(Bs[kk + tig + 4][nt * 8 + gid]);
                asm volatile(
                    "mma.sync.aligned.m16n8k8.row.col.f32.tf32.tf32.f32 "
                    "{%0,%1,%2,%3}, {%4,%5,%6,%7}, {%8,%9}, {%0,%1,%2,%3};"
                    : "+f"(c[nt][0]), "+f"(c[nt][1]), "+f"(c[nt][2]), "+f"(c[nt][3])
                    : "r"(a0), "r"(a1), "r"(a2), "r"(a3), "r"(b0), "r"(b1));
            }
        }
        __syncthreads();
    }

    // epilogue: bias, attribute_agg mix, store flow_all, fused score
    const int r1 = row0 + warp * 16 + gid;
    const int r2 = r1 + 8;
    float a0r1 = 0.f, a1r1 = 0.f, a0r2 = 0.f, a1r2 = 0.f;
    if (r1 < NN) { a0r1 = adj[r1]; a1r1 = adj[NN + r1]; }
    if (r2 < NN) { a0r2 = adj[r2]; a1r2 = adj[NN + r2]; }
    float s1 = 0.f, s2 = 0.f;
#pragma unroll
    for (int nt = 0; nt < 16; nt++) {
        const int col = nt * 8 + tig * 2;
        const float ch0a = ch_s[0][col], ch0b = ch_s[0][col + 1];
        const float ch1a = ch_s[1][col], ch1b = ch_s[1][col + 1];
        const float ba = bias_s[col], bbv = bias_s[col + 1];
        const float v1a = 0.5f * (c[nt][0] + ba  + a0r1 * ch0a + a1r1 * ch1a);
        const float v1b = 0.5f * (c[nt][1] + bbv + a0r1 * ch0b + a1r1 * ch1b);
        const float v2a = 0.5f * (c[nt][2] + ba  + a0r2 * ch0a + a1r2 * ch1a);
        const float v2b = 0.5f * (c[nt][3] + bbv + a0r2 * ch0b + a1r2 * ch1b);
        if (r1 < NN) *(float2*)&g_flow_all[(size_t)r1 * DD + col] = make_float2(v1a, v1b);
        if (r2 < NN) *(float2*)&g_flow_all[(size_t)r2 * DD + col] = make_float2(v2a, v2b);
        s1 += v1a * att_s[col] + v1b * att_s[col + 1];
        s2 += v2a * att_s[col] + v2b * att_s[col + 1];
    }
    s1 += __shfl_xor_sync(0xffffffffu, s1, 1);
    s1 += __shfl_xor_sync(0xffffffffu, s1, 2);
    s2 += __shfl_xor_sync(0xffffffffu, s2, 1);
    s2 += __shfl_xor_sync(0xffffffffu, s2, 2);
    if (tig == 0) {
        const float b0 = att1b[0];
        if (r1 < NN) g_score[r1] = s1 + b0;
        if (r2 < NN) g_score[r2] = s2 + b0;
    }
}

// ---------------- K6: per-row gather + softmax + weighted sum -> g_agg ----------------
__global__ __launch_bounds__(256) void agg_kernel(const int* __restrict__ history) {
    const int warp = threadIdx.x >> 5, lane = threadIdx.x & 31;
    const int b = blockIdx.x * 8 + warp;
    const int h = history[b * KK + lane];
    const float s = g_score[h];
    float mx = s;
#pragma unroll
    for (int o = 16; o; o >>= 1) mx = fmaxf(mx, __shfl_xor_sync(0xffffffffu, mx, o));
    const float e = expf(s - mx);
    float sum = e;
#pragma unroll
    for (int o = 16; o; o >>= 1) sum += __shfl_xor_sync(0xffffffffu, sum, o);
    const float att = e / sum;
    float4 acc = make_float4(0.f, 0.f, 0.f, 0.f);
    const float4* fa = (const float4*)g_flow_all;
#pragma unroll
    for (int k = 0; k < KK; k++) {
        const int   idx = __shfl_sync(0xffffffffu, h, k);
        const float w   = __shfl_sync(0xffffffffu, att, k);
        float4 f = fa[idx * 32 + lane];
        acc.x += w * f.x; acc.y += w * f.y; acc.z += w * f.z; acc.w += w * f.w;
    }
    ((float4*)g_agg)[b * 32 + lane] = acc;
}

// ---------------- K7: out = relu(agg @ (W1_top+W1_bot) + b1); preds fused ----------------
__global__ __launch_bounds__(256) void outpred_kernel(const float* __restrict__ lin1b,
                                                      float* __restrict__ out) {
    __shared__ __align__(16) float As[8][132];
    __shared__ __align__(16) float Bs[8][132];
    __shared__ __align__(16) float Lat_s[2 * MM * DD];
    __shared__ __align__(16) float lb_s[DD];
    const float* lw   = g_ptrs.lin1w;
    const int*   catr = g_ptrs.catr;
    const int*   catn = g_ptrs.catn;
    const int*   pav  = g_ptrs.pa;
    const int tid  = threadIdx.x;
    const int row0 = blockIdx.x * 128;
    for (int i = tid; i < 2 * MM * DD; i += 256) Lat_s[i] = g_Lat[i];
    if (tid < DD) lb_s[tid] = lin1b[tid];
    const int aRow = tid >> 1, aCol = (tid & 1) * 4;
    const int bRow = tid >> 5, bCol = (tid & 31) * 4;
    const int tx = tid & 15, ty = tid >> 4;

    float acc[8][8];
#pragma unroll
    for (int i = 0; i < 8; i++)
#pragma unroll
        for (int j = 0; j < 8; j++) acc[i][j] = 0.f;

    for (int kt = 0; kt < DD; kt += 8) {
        float4 av = *(const float4*)(g_agg + (size_t)(row0 + aRow) * DD + kt + aCol);
        As[aCol + 0][aRow] = av.x;
        As[aCol + 1][aRow] = av.y;
        As[aCol + 2][aRow] = av.z;
        As[aCol + 3][aRow] = av.w;
        float4 b0 = *(const float4*)(lw + (size_t)(kt + bRow) * DD + bCol);
        float4 b1 = *(const float4*)(lw + (size_t)(DD + kt + bRow) * DD + bCol);
        float4 bv = make_float4(b0.x + b1.x, b0.y + b1.y, b0.z + b1.z, b0.w + b1.w);
        *(float4*)(&Bs[bRow][bCol]) = bv;
        __syncthreads();
#pragma unroll
        for (int kk = 0; kk < 8; kk++) {
            float ra[8], rb[8];
            *(float4*)(ra)     = *(const float4*)(&As[kk][ty * 8]);
            *(float4*)(ra + 4) = *(const float4*)(&As[kk][ty * 8 + 4]);
            *(float4*)(rb)     = *(const float4*)(&Bs[kk][tx * 8]);
            *(float4*)(rb + 4) = *(const float4*)(&Bs[kk][tx * 8 + 4]);
#pragma unroll
            for (int i = 0; i < 8; i++)
#pragma unroll
                for (int j = 0; j < 8; j++) acc[i][j] += ra[i] * rb[j];
        }
        __syncthreads();
    }

    float pr[8], pn[8];
#pragma unroll
    for (int i = 0; i < 8; i++) {
        const int row = row0 + ty * 8 + i;
        const int cr  = catr[row];
        const int cn_ = catn[row];
        const int p_  = pav[row];
        const float4* Lr = (const float4*)&Lat_s[(cr * MM + p_) * DD];
        const float4* Ln = (const float4*)&Lat_s[(cn_ * MM + p_) * DD];
        float sr = 0.f, sn = 0.f;
#pragma unroll
        for (int jj = 0; jj < 2; jj++) {
            float4 l1 = Lr[tx * 2 + jj];
            float4 l2 = Ln[tx * 2 + jj];
            float4 bb = *(const float4*)&lb_s[tx * 8 + jj * 4];
            const float o0 = fmaxf(acc[i][jj * 4 + 0] + bb.x, 0.f);
            const float o1 = fmaxf(acc[i][jj * 4 + 1] + bb.y, 0.f);
            const float o2 = fmaxf(acc[i][jj * 4 + 2] + bb.z, 0.f);
            const float o3 = fmaxf(acc[i][jj * 4 + 3] + bb.w, 0.f);
            sr += l1.x * o0 + l1.y * o1 + l1.z * o2 + l1.w * o3;
            sn += l2.x * o0 + l2.y * o1 + l2.z * o2 + l2.w * o3;
        }
        pr[i] = sr;
        pn[i] = sn;
    }
#pragma unroll
    for (int off = 1; off < 16; off <<= 1) {
#pragma unroll
        for (int i = 0; i < 8; i++) {
            pr[i] += __shfl_xor_sync(0xffffffffu, pr[i], off);
            pn[i] += __shfl_xor_sync(0xffffffffu, pn[i], off);
        }
    }
    if (tx == 0) {
#pragma unroll
        for (int i = 0; i < 8; i++) {
            const int row = row0 + ty * 8 + i;
            out[row]      = pr[i];
            out[BB + row] = pn[i];
        }
    }
}

// ---------------- host ----------------
extern "C" void kernel_launch(void* const* d_in, const int* in_sizes, int n_in,
                              void* d_out, int out_size) {
    const float* feat = nullptr;
    const float* adj  = nullptr;
    const int*   hist = nullptr;
    const float* b1   = nullptr;
    const void*  s32[8] = {nullptr};
    int n32 = 0;
    const float* s128[4] = {nullptr};
    int n128 = 0;

    for (int i = 0; i < n_in; i++) {
        const int sz = in_sizes[i];
        if (sz == NN * FF)      feat = (const float*)d_in[i];
        else if (sz == MM * NN) adj  = (const float*)d_in[i];
        else if (sz == BB * KK) hist = (const int*)d_in[i];
        else if (sz == BB)      { if (n32 < 8)  s32[n32++]  = d_in[i]; }
        else if (sz == DD)      { if (n128 < 4) s128[n128++] = (const float*)d_in[i]; }
        else if (sz == 1)       b1 = (const float*)d_in[i];
    }
    // size-128 inputs keep the same relative order in both candidate layouts:
    const float* bemb  = s128[0];
    const float* att1w = s128[1];
    const float* lin1b = s128[2];

    fixup_kernel<<<1, 256>>>(s32[0], s32[1], s32[2], s32[3], s32[4], s32[5], s32[6]);
    adjfeat_kernel<<<(NN + 511) / 512, 256>>>(adj, feat);
    char_kernel2<<<MM, 128>>>(bemb);
    gemm_fused<<<(NN + 127) / 128, 256>>>(feat, bemb, adj, att1w, b1);
    lat_kernel2<<<MM + 2, 128>>>();
    sig_kernel<<<10, 256>>>();
    agg_kernel<<<BB / 8, 256>>>(hist);
    outpred_kernel<<<BB / 128, 256>>>(lin1b, (float*)d_out);
}